// round 1
// baseline (speedup 1.0000x reference)
#include <cuda_runtime.h>
#include <cuda_bf16.h>

// PepEmbedding: out[b,h,:] = soft_threshold(emb[x[b,h],:], s[x[b,h],:])
// soft_threshold(v, s) = sign(v) * relu(|v| - sigmoid(s))
//
// Shapes: x[16384,50] int32, emb[1e6,128] f32, s[1e6,128] f32, out[16384,50,128] f32.
// Mapping: 1 warp per gathered row; lane k handles float4 k (4 floats) of the
// 128-float row. All loads/stores are 128-bit and fully coalesced; the index
// load is a warp-uniform broadcast.

#define ROWS (16384 * 50)          // 819,200 gathered rows
#define VEC_PER_ROW 32             // 128 floats / 4

__device__ __forceinline__ float soft_thresh(float v, float sv) {
    // sigmoid via fast exp + fast reciprocal (MUFU x2); abs err ~1e-7 region,
    // far below the 1e-3 rel-err gate.
    float t = __fdividef(1.0f, 1.0f + __expf(-sv));
    float m = fabsf(v) - t;
    m = fmaxf(m, 0.0f);
    return copysignf(m, v);
}

__global__ __launch_bounds__(256, 8)
void pep_gather_kernel(const int* __restrict__ x,
                       const float4* __restrict__ emb,
                       const float4* __restrict__ s,
                       float4* __restrict__ out) {
    // global float4 id: gid = row * 32 + lane-chunk
    long long gid = (long long)blockIdx.x * blockDim.x + threadIdx.x;
    long long row  = gid >> 5;          // same for all 32 lanes of a warp
    int       comp = (int)(gid & 31);

    if (row >= ROWS) return;

    int idx = __ldg(&x[row]);           // warp-uniform broadcast load
    long long off = (long long)idx * VEC_PER_ROW + comp;

    float4 v = __ldg(&emb[off]);
    float4 t = __ldg(&s[off]);

    float4 o;
    o.x = soft_thresh(v.x, t.x);
    o.y = soft_thresh(v.y, t.y);
    o.z = soft_thresh(v.z, t.z);
    o.w = soft_thresh(v.w, t.w);

    out[gid] = o;
}

extern "C" void kernel_launch(void* const* d_in, const int* in_sizes, int n_in,
                              void* d_out, int out_size) {
    const int*    x   = (const int*)d_in[0];
    const float4* emb = (const float4*)d_in[1];
    const float4* s   = (const float4*)d_in[2];
    float4*       out = (float4*)d_out;

    const long long total_vec = (long long)ROWS * VEC_PER_ROW;  // 26,214,400
    const int threads = 256;
    const int blocks = (int)((total_vec + threads - 1) / threads); // 102,400

    pep_gather_kernel<<<blocks, threads>>>(x, emb, s, out);
}